// round 15
// baseline (speedup 1.0000x reference)
#include <cuda_runtime.h>
#include <math.h>

#define BATCH 16
#define NPIX  262144        // 512*512
#define CHUNKS 32           // grid 512 = single wave at 4 blocks/SM
#define PXB   (NPIX / CHUNKS / 4)   // uint4/float4 positions per block = 2048
#define TPB   256
#define NBIN1 16
#define NBIN2 4096
#define FULLMASK 0xFFFFFFFFu
#define INV65534 (1.0f/65534.0f)
#define MAGICF  12582912.0f  // 1.5 * 2^23: FFMA(p,65534,MAGIC) -> int in low mantissa

// ---------------- global scratch (static; no allocation) --------------------
// INVARIANT: all accumulated globals below are ZERO at kernel_launch entry.
// CUDA zero-initializes device globals at load; afterwards each replay's last
// reader restores the zeros (kernelDE: hist2/hist1/sumA/scalars/done).
__device__ uint4 g_packA[BATCH * NPIX / 4];   // per px: q0 | q1<<16
__device__ uint4 g_packB[BATCH * NPIX / 4];   // per px: q2 | q3<<16
__device__ uint2 g_packC[BATCH * NPIX / 4];   // per 2 px: q4 | q4'<<16
__device__ int   g_hist1[BATCH][5][NBIN1];
__device__ int   g_hist2[BATCH][5][NBIN2];
__device__ int   g_cnt[BATCH];
__device__ float g_clsSum[BATCH][4];
__device__ float g_sevSum[BATCH];
__device__ int   g_clsMax[BATCH][4];
__device__ int   g_sevMax[BATCH];
__device__ float g_dmg[BATCH], g_high[BATCH];
__device__ float g_sumA[BATCH][5];            // sum of t=q-1 over above-bin elems
__device__ float g_topk[BATCH][5];            // plain write, no init needed
__device__ int   g_done[BATCH];               // last-block counter (self-clean)

// ---------------- pass A ----------------------------------------------------
__global__ void __launch_bounds__(TPB)
passA(const float* __restrict__ logits,
      const float* __restrict__ sev,
      const float* __restrict__ mask) {
    __shared__ unsigned char hcnt[5 * 4096 + 1024];   // 21.5 KB
    __shared__ float red[13 * 8];

    const int b = blockIdx.y, chunk = blockIdx.x, tid = threadIdx.x;
    const int warp = tid >> 5, lane = tid & 31;
    const int wl = warp * 128 + lane * 4;

    int* hw = (int*)hcnt;
#pragma unroll
    for (int i = tid; i < (5 * 4096 + 1024) / 4; i += TPB) hw[i] = 0;
    __syncthreads();

    const float4* L0 = (const float4*)(logits + (size_t)b * 4 * NPIX);
    const float4* L1 = (const float4*)(logits + (size_t)b * 4 * NPIX + NPIX);
    const float4* L2 = (const float4*)(logits + (size_t)b * 4 * NPIX + 2 * NPIX);
    const float4* L3 = (const float4*)(logits + (size_t)b * 4 * NPIX + 3 * NPIX);
    const float4* SV = (const float4*)(sev  + (size_t)b * NPIX);
    const float4* MK = (const float4*)(mask + (size_t)b * NPIX);
    uint4* PA = g_packA + (size_t)b * (NPIX / 4);
    uint4* PB = g_packB + (size_t)b * (NPIX / 4);
    uint2* PC = g_packC + (size_t)b * (NPIX / 4);

    const int fbase = chunk * PXB + tid;

    float cs0 = 0, cs1 = 0, cs2 = 0, cs3 = 0, ssum = 0, dmg = 0, hgh = 0;
    float m0 = 0, m1 = 0, m2 = 0, m3 = 0, smax = 0, fcnt = 0;

#pragma unroll 4
    for (int it = 0; it < PXB / TPB; ++it) {
        const int fi = fbase + it * 256;
        float4 a0 = L0[fi], a1 = L1[fi], a2 = L2[fi], a3 = L3[fi];
        float4 mm = MK[fi], vv = SV[fi];
        unsigned w01[4], w23[4], q4s[4];
#pragma unroll
        for (int p = 0; p < 4; ++p) {
            float l0 = ((const float*)&a0)[p];
            float l1 = ((const float*)&a1)[p];
            float l2 = ((const float*)&a2)[p];
            float l3 = ((const float*)&a3)[p];
            float mv = ((const float*)&mm)[p];
            float sq = ((const float*)&vv)[p];
            bool valid = mv > 0.5f;
            float vf = valid ? 1.f : 0.f;

            // logits are N(0,1): |l| < ~6, exp() safe without max-shift
            float e0 = __expf(l0), e1 = __expf(l1);
            float e2 = __expf(l2), e3 = __expf(l3);
            float inv = __fdividef(1.0f, e0 + e1 + e2 + e3);
            float p0 = e0 * inv, p1 = e1 * inv, p2 = e2 * inv, p3 = e3 * inv;
            float sg = __fdividef(1.0f, 1.0f + __expf(-sq));

            fcnt += vf;
            cs0 += vf * p0; cs1 += vf * p1; cs2 += vf * p2; cs3 += vf * p3;
            ssum += vf * sg;
            m0 = fmaxf(m0, vf * p0); m1 = fmaxf(m1, vf * p1);
            m2 = fmaxf(m2, vf * p2); m3 = fmaxf(m3, vf * p3);
            smax = fmaxf(smax, vf * sg);
            // p1+p2+p3 > 0.25  <=>  p0 < 0.75   (sum = 1)
            dmg += (p0 < 0.75f) ? vf : 0.f;
            // p2+p3 > 0.25  <=>  p0+p1 < 0.75
            hgh += (p0 + p1 < 0.75f) ? vf : 0.f;

            // magic-number round-to-nearest-even quantization (no F2I)
            unsigned n0 = __float_as_uint(fmaf(p0, 65534.f, MAGICF)) & 0xFFFFu;
            unsigned n1 = __float_as_uint(fmaf(p1, 65534.f, MAGICF)) & 0xFFFFu;
            unsigned n2 = __float_as_uint(fmaf(p2, 65534.f, MAGICF)) & 0xFFFFu;
            unsigned n3 = __float_as_uint(fmaf(p3, 65534.f, MAGICF)) & 0xFFFFu;
            unsigned n4 = __float_as_uint(fmaf(sg, 65534.f, MAGICF)) & 0xFFFFu;
            unsigned q0 = valid ? n0 + 1u : 0u;
            unsigned q1 = valid ? n1 + 1u : 0u;
            unsigned q2 = valid ? n2 + 1u : 0u;
            unsigned q3 = valid ? n3 + 1u : 0u;
            unsigned q4 = valid ? n4 + 1u : 0u;

#define HINC(CH, N) { \
            unsigned bin_ = (N) >> 12; \
            int idx_ = valid ? (CH) * 4096 + (int)(((bin_ >> 2) << 10) + wl + (bin_ & 3)) \
                             : 20480 + wl + ((CH) & 3); \
            hcnt[idx_]++; }
            HINC(0, n0) HINC(1, n1) HINC(2, n2) HINC(3, n3) HINC(4, n4)
#undef HINC

            w01[p] = q0 | (q1 << 16);
            w23[p] = q2 | (q3 << 16);
            q4s[p] = q4;
        }
        PA[fi] = make_uint4(w01[0], w01[1], w01[2], w01[3]);
        PB[fi] = make_uint4(w23[0], w23[1], w23[2], w23[3]);
        PC[fi] = make_uint2(q4s[0] | (q4s[1] << 16), q4s[2] | (q4s[3] << 16));
    }
    __syncthreads();

    // merge byte hist -> global level-1 (dp4a byte extraction)
    if (tid < 80) {
        int ch = tid >> 4, bin = tid & 15;
        int basew = ch * 1024 + (bin >> 2) * 256;
        int bsel = 1 << (8 * (bin & 3));
        int acc = 0;
#pragma unroll 8
        for (int i = 0; i < 256; ++i) acc = __dp4a(hw[basew + i], bsel, acc);
        atomicAdd(&g_hist1[b][ch][bin], acc);
    }

    // scalar stat reductions
    float sums[8] = {fcnt, cs0, cs1, cs2, cs3, ssum, dmg, hgh};
    float maxs[5] = {m0, m1, m2, m3, smax};
#pragma unroll
    for (int s = 0; s < 8; ++s) {
        float v = sums[s];
        for (int o = 16; o; o >>= 1) v += __shfl_down_sync(FULLMASK, v, o);
        if (lane == 0) red[s * 8 + warp] = v;
    }
#pragma unroll
    for (int s = 0; s < 5; ++s) {
        float v = maxs[s];
        for (int o = 16; o; o >>= 1) v = fmaxf(v, __shfl_down_sync(FULLMASK, v, o));
        if (lane == 0) red[(8 + s) * 8 + warp] = v;
    }
    __syncthreads();
    if (tid < 13) {
        float v = red[tid * 8];
        if (tid < 8) { for (int w2 = 1; w2 < 8; ++w2) v += red[tid * 8 + w2]; }
        else         { for (int w2 = 1; w2 < 8; ++w2) v = fmaxf(v, red[tid * 8 + w2]); }
        if (tid == 0)      atomicAdd(&g_cnt[b], (int)v);
        else if (tid < 5)  atomicAdd(&g_clsSum[b][tid - 1], v);
        else if (tid == 5) atomicAdd(&g_sevSum[b], v);
        else if (tid == 6) atomicAdd(&g_dmg[b], v);
        else if (tid == 7) atomicAdd(&g_high[b], v);
        else if (tid < 12) atomicMax(&g_clsMax[b][tid - 8], __float_as_int(v));
        else               atomicMax(&g_sevMax[b], __float_as_int(v));
    }
}

// ---------------- pass C: SIMD sum-above + rare global refine atomics -------
__global__ void __launch_bounds__(TPB)
passC() {
    __shared__ int sT[5], sL[5];
    __shared__ int red[5 * 8];
    const int b = blockIdx.y, chunk = blockIdx.x, tid = threadIdx.x;
    const int warp = tid >> 5, lane = tid & 31;

    if (tid < 5) {
        int total = g_cnt[b];
        int k = max(1, (int)rintf((float)total * 0.1f));
        int j1 = -1, cum = 0;
        if (total > 0) {
            for (int bin = 15; bin >= 0; --bin) {
                int c = g_hist1[b][tid][bin];
                if (cum + c >= k) { j1 = bin; break; }
                cum += c;
            }
        }
        sT[tid] = (j1 >= 0) ? min((j1 + 1) << 12, 65535) : 65535;
        sL[tid] = (j1 >= 0) ? (j1 << 12) : 65535;
    }
    __syncthreads();

    const unsigned TT01 = (unsigned)sT[0] | ((unsigned)sT[1] << 16);
    const unsigned LL01 = (unsigned)sL[0] | ((unsigned)sL[1] << 16);
    const unsigned TT23 = (unsigned)sT[2] | ((unsigned)sT[3] << 16);
    const unsigned LL23 = (unsigned)sL[2] | ((unsigned)sL[3] << 16);
    const unsigned TT44 = (unsigned)sT[4] | ((unsigned)sT[4] << 16);
    const unsigned LL44 = (unsigned)sL[4] | ((unsigned)sL[4] << 16);
    const int L0 = sL[0], L1 = sL[1], L2 = sL[2], L3 = sL[3], L4 = sL[4];

    const uint4* PA = g_packA + (size_t)b * (NPIX / 4);
    const uint4* PB = g_packB + (size_t)b * (NPIX / 4);
    const uint2* PC = g_packC + (size_t)b * (NPIX / 4);
    int* H0 = g_hist2[b][0]; int* H1 = g_hist2[b][1]; int* H2 = g_hist2[b][2];
    int* H3 = g_hist2[b][3]; int* H4 = g_hist2[b][4];

    unsigned s0 = 0, s1 = 0, s2 = 0, s3 = 0, s4 = 0;
    unsigned c01 = 0, c23 = 0, c44 = 0;
    const int fbase = chunk * PXB + tid;

#define PROCW(W, TT, LL, SLO, SHI, CACC, HLO, HHI, LLO, LHI) { \
    unsigned m_ = __vcmpgtu2((W), (TT)); \
    unsigned sel_ = (W) & m_; \
    SLO += sel_ & 0xFFFFu; SHI += sel_ >> 16; \
    CACC += m_ & 0x00010001u; \
    unsigned im_ = __vcmpgtu2((W), (LL)) ^ m_; \
    if (im_ & 0xFFFFu)      atomicAdd((HLO) + (int)(((W) & 0xFFFFu) - 1u) - (LLO), 1); \
    if (im_ & 0xFFFF0000u)  atomicAdd((HHI) + (int)((W) >> 16) - 1 - (LHI), 1); }

#pragma unroll 4
    for (int it = 0; it < PXB / TPB; ++it) {
        const int fi = fbase + it * 256;
        uint4 A = PA[fi], B = PB[fi];
        uint2 C = PC[fi];
        PROCW(A.x, TT01, LL01, s0, s1, c01, H0, H1, L0, L1)
        PROCW(A.y, TT01, LL01, s0, s1, c01, H0, H1, L0, L1)
        PROCW(A.z, TT01, LL01, s0, s1, c01, H0, H1, L0, L1)
        PROCW(A.w, TT01, LL01, s0, s1, c01, H0, H1, L0, L1)
        PROCW(B.x, TT23, LL23, s2, s3, c23, H2, H3, L2, L3)
        PROCW(B.y, TT23, LL23, s2, s3, c23, H2, H3, L2, L3)
        PROCW(B.z, TT23, LL23, s2, s3, c23, H2, H3, L2, L3)
        PROCW(B.w, TT23, LL23, s2, s3, c23, H2, H3, L2, L3)
        PROCW(C.x, TT44, LL44, s4, s4, c44, H4, H4, L4, L4)
        PROCW(C.y, TT44, LL44, s4, s4, c44, H4, H4, L4, L4)
    }
#undef PROCW

    int sAt[5];
    sAt[0] = (int)(s0 - (c01 & 0xFFFFu));
    sAt[1] = (int)(s1 - (c01 >> 16));
    sAt[2] = (int)(s2 - (c23 & 0xFFFFu));
    sAt[3] = (int)(s3 - (c23 >> 16));
    sAt[4] = (int)(s4 - ((c44 & 0xFFFFu) + (c44 >> 16)));

#pragma unroll
    for (int ch = 0; ch < 5; ++ch) {
        int v = sAt[ch];
        for (int o = 16; o; o >>= 1) v += __shfl_down_sync(FULLMASK, v, o);
        if (lane == 0) red[ch * 8 + warp] = v;
    }
    __syncthreads();
    if (tid < 5) {
        int v = 0;
        for (int w2 = 0; w2 < 8; ++w2) v += red[tid * 8 + w2];
        atomicAdd(&g_sumA[b][tid], (float)v);
    }
}

// ---------------- kernel DE: topk scan + (last block per batch) stats/MLP ---
// 80 blocks (one per (b,ch)). D-scan register-resident + self-cleaning; the
// LAST finisher per batch continues into the E body (stats/LN/MLP/outputs).
__global__ void __launch_bounds__(256, 1)
kernelDE(const float* __restrict__ ln_w, const float* __restrict__ ln_b,
         const float* __restrict__ w1,   const float* __restrict__ b1,
         const float* __restrict__ w2,   const float* __restrict__ b2,
         float* __restrict__ out) {
    __shared__ int wtot[8];
    __shared__ float scontrib[8];
    __shared__ int sInfo[2];   // r, j1
    __shared__ int sLast;
    const int bc = blockIdx.x, b = bc / 5, ch = bc % 5;
    const int tid = threadIdx.x, warp = tid >> 5, lane = tid & 31;
    int* __restrict__ H = g_hist2[b][ch];

    if (tid == 0) {
        int total = g_cnt[b];
        int k = max(1, (int)rintf((float)total * 0.1f));
        int j1 = -1, cum = 0;
        if (total > 0) {
            for (int bin = 15; bin >= 0; --bin) {
                int c = g_hist1[b][ch][bin];
                if (cum + c >= k) { j1 = bin; break; }
                cum += c;
            }
        }
        sInfo[0] = k - cum;   // r
        sInfo[1] = j1;
    }

    // load 16 bins into registers; local count + weighted sum; zero behind us
    const int lo = 4080 - 16 * tid;
    int v[16];
    int cnt = 0; float wsum = 0.f;
    int4* H4 = (int4*)(H + lo);
    const int4 zero4 = make_int4(0, 0, 0, 0);
#pragma unroll
    for (int i = 0; i < 4; ++i) {
        int4 t = H4[i];
        v[4 * i] = t.x; v[4 * i + 1] = t.y; v[4 * i + 2] = t.z; v[4 * i + 3] = t.w;
        int code = lo + 4 * i;
        cnt += t.x + t.y + t.z + t.w;
        wsum += (float)t.x * (float)code + (float)t.y * (float)(code + 1)
              + (float)t.z * (float)(code + 2) + (float)t.w * (float)(code + 3);
        H4[i] = zero4;   // self-clean (thread-exclusive bins)
    }

    // inclusive prefix over 256 threads (warp shfl scan + warp-total offsets)
    int incl = cnt;
#pragma unroll
    for (int o = 1; o < 32; o <<= 1) {
        int t = __shfl_up_sync(FULLMASK, incl, o);
        if (lane >= o) incl += t;
    }
    if (lane == 31) wtot[warp] = incl;
    __syncthreads();
    // hist1[b][ch] fully consumed by tid 0 before the barrier -> zero it now
    if (tid >= 32 && tid < 48) g_hist1[b][ch][tid - 32] = 0;
    int woff = 0;
#pragma unroll
    for (int w = 0; w < 8; ++w) woff += (w < warp) ? wtot[w] : 0;
    incl += woff;
    const int excl = incl - cnt;

    const int r = sInfo[0], j1 = sInfo[1];
    float contrib = 0.f;
    if (j1 >= 0) {
        if (incl <= r) {
            contrib = wsum;
        } else if (excl < r) {
            int need = r - excl;
#pragma unroll
            for (int i = 15; i >= 0; --i) {
                int take = max(0, min(v[i], need));
                contrib += (float)take * (float)(lo + i);
                need -= take;
            }
        }
    }
    // block reduce contributions
    for (int o = 16; o; o >>= 1) contrib += __shfl_down_sync(FULLMASK, contrib, o);
    if (lane == 0) scontrib[warp] = contrib;
    __syncthreads();
    if (tid == 0) {
        float sA = g_sumA[b][ch];
        g_sumA[b][ch] = 0.f;          // same-thread same-address: safe
        float tk = 0.f;
        if (j1 >= 0) {
            float rs = 0.f;
#pragma unroll
            for (int w = 0; w < 8; ++w) rs += scontrib[w];
            int total = g_cnt[b];
            int k = max(1, (int)rintf((float)total * 0.1f));
            float full = rs + (float)r * (float)(j1 << 12);
            tk = (sA + full) * INV65534 / (float)k;
        }
        g_topk[b][ch] = tk;
        __threadfence();              // publish topk before counter bump
        int old = atomicAdd(&g_done[b], 1);
        sLast = (old == 4) ? 1 : 0;
    }
    __syncthreads();
    if (!sLast) return;

    // ================= E body: this block is the last finisher for batch b ==
    __shared__ float stats[18], normed[18], h1s[256];
    __shared__ float4 sred[256];

    if (tid < 32) {
        __threadfence();              // acquire: make peers' g_topk visible
        // ---- PHASE 1: ALL reads into registers (no stores yet) ----
        const int total = g_cnt[b];
        const float st = fmaxf((float)total, 1.f);
        float val = 0.f;
        if (tid < 4)        val = g_clsSum[b][tid] / st;
        else if (tid < 8)   val = __int_as_float(g_clsMax[b][tid - 4]);
        else if (tid < 12)  val = g_topk[b][tid - 8];
        else if (tid == 12) val = g_sevSum[b] / st;
        else if (tid == 13) val = __int_as_float(g_sevMax[b]);
        else if (tid == 14) val = g_topk[b][4];
        else if (tid == 15) val = g_dmg[b] / st;
        else if (tid == 16) val = g_high[b] / st;
        else if (tid == 17) val = (float)total / (float)NPIX;

        __syncwarp();                 // reads complete before self-clean stores

        // ---- PHASE 2: self-clean stores ----
        if (tid < 4)        g_clsSum[b][tid] = 0.f;
        else if (tid < 8)   g_clsMax[b][tid - 4] = 0;
        else if (tid == 12) g_sevSum[b] = 0.f;
        else if (tid == 13) g_sevMax[b] = 0;
        else if (tid == 15) g_dmg[b] = 0.f;
        else if (tid == 16) g_high[b] = 0.f;
        else if (tid == 17) g_cnt[b] = 0;
        else if (tid == 18) g_done[b] = 0;

        if (tid < 18) stats[tid] = val;

        // LN via warp reductions (lanes >=18 contribute 0)
        float x = (tid < 18) ? val : 0.f;
        float s = x;
#pragma unroll
        for (int o = 16; o; o >>= 1) s += __shfl_xor_sync(FULLMASK, s, o);
        float mu = s * (1.0f / 18.0f);
        float d = (tid < 18) ? (x - mu) : 0.f;
        float vsum = d * d;
#pragma unroll
        for (int o = 16; o; o >>= 1) vsum += __shfl_xor_sync(FULLMASK, vsum, o);
        float rstd = rsqrtf(vsum * (1.0f / 18.0f) + 1e-5f);
        if (tid < 18) normed[tid] = (x - mu) * rstd * ln_w[tid] + ln_b[tid];
    }
    __syncthreads();

    // layer 1: 18 -> 256, exact gelu
    {
        float a0 = b1[tid], a1 = 0.f;
#pragma unroll
        for (int i = 0; i < 18; i += 2) {
            a0 = fmaf(normed[i],     w1[i * 256 + tid],       a0);
            a1 = fmaf(normed[i + 1], w1[(i + 1) * 256 + tid], a1);
        }
        float acc = a0 + a1;
        h1s[tid] = 0.5f * acc * (1.0f + erff(acc * 0.70710678118654752f));
    }
    __syncthreads();

    // layer 2: 256 -> 256. Double-buffered float4 loads of w2.
    {
        const int g = tid >> 6, j = tid & 63;
        const float4* __restrict__ W2 =
            (const float4*)w2 + (size_t)(g * 64) * 64 + j;   // step 64 per k
        float4 cur[4], nxt[4];
#pragma unroll
        for (int q = 0; q < 4; ++q) cur[q] = W2[q * 64];
        float4 c0 = make_float4(0.f, 0.f, 0.f, 0.f);
        float4 c1 = make_float4(0.f, 0.f, 0.f, 0.f);
#pragma unroll
        for (int base = 0; base < 64; base += 4) {
            if (base + 4 < 64) {
#pragma unroll
                for (int q = 0; q < 4; ++q) nxt[q] = W2[(base + 4 + q) * 64];
            }
#pragma unroll
            for (int q = 0; q < 4; ++q) {
                const float h = h1s[g * 64 + base + q];
                float4 w = cur[q];
                if (q & 1) {
                    c1.x = fmaf(h, w.x, c1.x); c1.y = fmaf(h, w.y, c1.y);
                    c1.z = fmaf(h, w.z, c1.z); c1.w = fmaf(h, w.w, c1.w);
                } else {
                    c0.x = fmaf(h, w.x, c0.x); c0.y = fmaf(h, w.y, c0.y);
                    c0.z = fmaf(h, w.z, c0.z); c0.w = fmaf(h, w.w, c0.w);
                }
            }
#pragma unroll
            for (int q = 0; q < 4; ++q) cur[q] = nxt[q];
        }
        sred[tid] = make_float4(c0.x + c1.x, c0.y + c1.y, c0.z + c1.z, c0.w + c1.w);
    }
    __syncthreads();
    if (tid < 64) {
        const int j = tid;
        float4 c0 = sred[j], c1 = sred[64 + j], c2 = sred[128 + j], c3 = sred[192 + j];
        float4 bb = ((const float4*)b2)[j];
        float4 r4;
        r4.x = bb.x + ((c0.x + c1.x) + (c2.x + c3.x));
        r4.y = bb.y + ((c0.y + c1.y) + (c2.y + c3.y));
        r4.z = bb.z + ((c0.z + c1.z) + (c2.z + c3.z));
        r4.w = bb.w + ((c0.w + c1.w) + (c2.w + c3.w));
        ((float4*)(out + BATCH * 18 + b * 256))[j] = r4;
    }
    if (tid < 18) out[b * 18 + tid] = stats[tid];
    if (tid == 0) {
        const int base = BATCH * 18 + BATCH * 256;
        out[base + b]             = stats[15];
        out[base + BATCH + b]     = stats[16];
        out[base + 2 * BATCH + b] = stats[17];
    }
}

// ---------------- launch ----------------------------------------------------
extern "C" void kernel_launch(void* const* d_in, const int* in_sizes, int n_in,
                              void* d_out, int out_size) {
    const float* logits = (const float*)d_in[0];
    const float* sevm   = (const float*)d_in[1];
    const float* maskm  = (const float*)d_in[2];
    const float* ln_w   = (const float*)d_in[3];
    const float* ln_b   = (const float*)d_in[4];
    const float* w1     = (const float*)d_in[5];
    const float* b1     = (const float*)d_in[6];
    const float* w2     = (const float*)d_in[7];
    const float* b2     = (const float*)d_in[8];
    float* out = (float*)d_out;

    dim3 g(CHUNKS, BATCH);
    passA<<<g, TPB>>>(logits, sevm, maskm);
    passC<<<g, TPB>>>();
    kernelDE<<<80, 256>>>(ln_w, ln_b, w1, b1, w2, b2, out);
}

// round 16
// speedup vs baseline: 1.1189x; 1.1189x over previous
#include <cuda_runtime.h>
#include <math.h>

#define BATCH 16
#define NPIX  262144        // 512*512
#define CHUNKS 32           // grid 512 = single wave at 4 blocks/SM (pinned)
#define PXB   (NPIX / CHUNKS / 4)   // uint4/float4 positions per block = 2048
#define TPB   256
#define NBIN1 16
#define NBIN2 4096
#define FULLMASK 0xFFFFFFFFu
#define INV65534 (1.0f/65534.0f)
#define MAGICF  12582912.0f  // 1.5 * 2^23: FFMA(p,65534,MAGIC) -> int in low mantissa

// ---------------- global scratch (static; no allocation) --------------------
// INVARIANT: all accumulated globals below are ZERO at kernel_launch entry.
// CUDA zero-initializes device globals at load; afterwards each replay's last
// reader restores the zeros (kernelDE: hist2/hist1/sumA/scalars/done).
__device__ uint4 g_packA[BATCH * NPIX / 4];   // per px: q0 | q1<<16
__device__ uint4 g_packB[BATCH * NPIX / 4];   // per px: q2 | q3<<16
__device__ uint2 g_packC[BATCH * NPIX / 4];   // per 2 px: q4 | q4'<<16
__device__ int   g_hist1[BATCH][5][NBIN1];
__device__ int   g_hist2[BATCH][5][NBIN2];
__device__ int   g_cnt[BATCH];
__device__ float g_clsSum[BATCH][4];
__device__ float g_sevSum[BATCH];
__device__ int   g_clsMax[BATCH][4];
__device__ int   g_sevMax[BATCH];
__device__ float g_dmg[BATCH], g_high[BATCH];
__device__ float g_sumA[BATCH][5];            // sum of t=q-1 over above-bin elems
__device__ float g_topk[BATCH][5];            // plain write, no init needed
__device__ int   g_done[BATCH];               // last-block counter (self-clean)

// ---------------- pass A ----------------------------------------------------
// __launch_bounds__(TPB, 4): pin 4 blocks/SM (<=64 regs) so grid 512 runs as
// ONE wave on 148 SMs (R15 regression root cause: 77 regs -> 3 blk/SM -> tail wave).
__global__ void __launch_bounds__(TPB, 4)
passA(const float* __restrict__ logits,
      const float* __restrict__ sev,
      const float* __restrict__ mask) {
    __shared__ unsigned char hcnt[5 * 4096 + 1024];   // 21.5 KB
    __shared__ float red[13 * 8];

    const int b = blockIdx.y, chunk = blockIdx.x, tid = threadIdx.x;
    const int warp = tid >> 5, lane = tid & 31;
    const int wl = warp * 128 + lane * 4;

    int* hw = (int*)hcnt;
#pragma unroll
    for (int i = tid; i < (5 * 4096 + 1024) / 4; i += TPB) hw[i] = 0;
    __syncthreads();

    const float4* L0 = (const float4*)(logits + (size_t)b * 4 * NPIX);
    const float4* L1 = (const float4*)(logits + (size_t)b * 4 * NPIX + NPIX);
    const float4* L2 = (const float4*)(logits + (size_t)b * 4 * NPIX + 2 * NPIX);
    const float4* L3 = (const float4*)(logits + (size_t)b * 4 * NPIX + 3 * NPIX);
    const float4* SV = (const float4*)(sev  + (size_t)b * NPIX);
    const float4* MK = (const float4*)(mask + (size_t)b * NPIX);
    uint4* PA = g_packA + (size_t)b * (NPIX / 4);
    uint4* PB = g_packB + (size_t)b * (NPIX / 4);
    uint2* PC = g_packC + (size_t)b * (NPIX / 4);

    const int fbase = chunk * PXB + tid;

    float cs0 = 0, cs1 = 0, cs2 = 0, cs3 = 0, ssum = 0, dmg = 0, hgh = 0;
    float m0 = 0, m1 = 0, m2 = 0, m3 = 0, smax = 0, fcnt = 0;

#pragma unroll 2
    for (int it = 0; it < PXB / TPB; ++it) {
        const int fi = fbase + it * 256;
        float4 a0 = L0[fi], a1 = L1[fi], a2 = L2[fi], a3 = L3[fi];
        float4 mm = MK[fi], vv = SV[fi];
        unsigned w01[4], w23[4], q4s[4];
#pragma unroll
        for (int p = 0; p < 4; ++p) {
            float l0 = ((const float*)&a0)[p];
            float l1 = ((const float*)&a1)[p];
            float l2 = ((const float*)&a2)[p];
            float l3 = ((const float*)&a3)[p];
            float mv = ((const float*)&mm)[p];
            float sq = ((const float*)&vv)[p];
            bool valid = mv > 0.5f;
            float vf = valid ? 1.f : 0.f;

            // logits are N(0,1): |l| < ~6, exp() safe without max-shift
            float e0 = __expf(l0), e1 = __expf(l1);
            float e2 = __expf(l2), e3 = __expf(l3);
            float inv = __fdividef(1.0f, e0 + e1 + e2 + e3);
            float p0 = e0 * inv, p1 = e1 * inv, p2 = e2 * inv, p3 = e3 * inv;
            float sg = __fdividef(1.0f, 1.0f + __expf(-sq));

            fcnt += vf;
            cs0 += vf * p0; cs1 += vf * p1; cs2 += vf * p2; cs3 += vf * p3;
            ssum += vf * sg;
            m0 = fmaxf(m0, vf * p0); m1 = fmaxf(m1, vf * p1);
            m2 = fmaxf(m2, vf * p2); m3 = fmaxf(m3, vf * p3);
            smax = fmaxf(smax, vf * sg);
            // p1+p2+p3 > 0.25  <=>  p0 < 0.75   (sum = 1)
            dmg += (p0 < 0.75f) ? vf : 0.f;
            // p2+p3 > 0.25  <=>  p0+p1 < 0.75
            hgh += (p0 + p1 < 0.75f) ? vf : 0.f;

            // magic-number round-to-nearest-even quantization (no F2I)
            unsigned n0 = __float_as_uint(fmaf(p0, 65534.f, MAGICF)) & 0xFFFFu;
            unsigned n1 = __float_as_uint(fmaf(p1, 65534.f, MAGICF)) & 0xFFFFu;
            unsigned n2 = __float_as_uint(fmaf(p2, 65534.f, MAGICF)) & 0xFFFFu;
            unsigned n3 = __float_as_uint(fmaf(p3, 65534.f, MAGICF)) & 0xFFFFu;
            unsigned n4 = __float_as_uint(fmaf(sg, 65534.f, MAGICF)) & 0xFFFFu;
            unsigned q0 = valid ? n0 + 1u : 0u;
            unsigned q1 = valid ? n1 + 1u : 0u;
            unsigned q2 = valid ? n2 + 1u : 0u;
            unsigned q3 = valid ? n3 + 1u : 0u;
            unsigned q4 = valid ? n4 + 1u : 0u;

#define HINC(CH, N) { \
            unsigned bin_ = (N) >> 12; \
            int idx_ = valid ? (CH) * 4096 + (int)(((bin_ >> 2) << 10) + wl + (bin_ & 3)) \
                             : 20480 + wl + ((CH) & 3); \
            hcnt[idx_]++; }
            HINC(0, n0) HINC(1, n1) HINC(2, n2) HINC(3, n3) HINC(4, n4)
#undef HINC

            w01[p] = q0 | (q1 << 16);
            w23[p] = q2 | (q3 << 16);
            q4s[p] = q4;
        }
        PA[fi] = make_uint4(w01[0], w01[1], w01[2], w01[3]);
        PB[fi] = make_uint4(w23[0], w23[1], w23[2], w23[3]);
        PC[fi] = make_uint2(q4s[0] | (q4s[1] << 16), q4s[2] | (q4s[3] << 16));
    }
    __syncthreads();

    // merge byte hist -> global level-1 (dp4a byte extraction)
    if (tid < 80) {
        int ch = tid >> 4, bin = tid & 15;
        int basew = ch * 1024 + (bin >> 2) * 256;
        int bsel = 1 << (8 * (bin & 3));
        int acc = 0;
#pragma unroll 8
        for (int i = 0; i < 256; ++i) acc = __dp4a(hw[basew + i], bsel, acc);
        atomicAdd(&g_hist1[b][ch][bin], acc);
    }

    // scalar stat reductions
    float sums[8] = {fcnt, cs0, cs1, cs2, cs3, ssum, dmg, hgh};
    float maxs[5] = {m0, m1, m2, m3, smax};
#pragma unroll
    for (int s = 0; s < 8; ++s) {
        float v = sums[s];
        for (int o = 16; o; o >>= 1) v += __shfl_down_sync(FULLMASK, v, o);
        if (lane == 0) red[s * 8 + warp] = v;
    }
#pragma unroll
    for (int s = 0; s < 5; ++s) {
        float v = maxs[s];
        for (int o = 16; o; o >>= 1) v = fmaxf(v, __shfl_down_sync(FULLMASK, v, o));
        if (lane == 0) red[(8 + s) * 8 + warp] = v;
    }
    __syncthreads();
    if (tid < 13) {
        float v = red[tid * 8];
        if (tid < 8) { for (int w2 = 1; w2 < 8; ++w2) v += red[tid * 8 + w2]; }
        else         { for (int w2 = 1; w2 < 8; ++w2) v = fmaxf(v, red[tid * 8 + w2]); }
        if (tid == 0)      atomicAdd(&g_cnt[b], (int)v);
        else if (tid < 5)  atomicAdd(&g_clsSum[b][tid - 1], v);
        else if (tid == 5) atomicAdd(&g_sevSum[b], v);
        else if (tid == 6) atomicAdd(&g_dmg[b], v);
        else if (tid == 7) atomicAdd(&g_high[b], v);
        else if (tid < 12) atomicMax(&g_clsMax[b][tid - 8], __float_as_int(v));
        else               atomicMax(&g_sevMax[b], __float_as_int(v));
    }
}

// ---------------- pass C: SIMD sum-above + rare global refine atomics -------
__global__ void __launch_bounds__(TPB, 4)
passC() {
    __shared__ int sT[5], sL[5];
    __shared__ int red[5 * 8];
    const int b = blockIdx.y, chunk = blockIdx.x, tid = threadIdx.x;
    const int warp = tid >> 5, lane = tid & 31;

    if (tid < 5) {
        int total = g_cnt[b];
        int k = max(1, (int)rintf((float)total * 0.1f));
        int j1 = -1, cum = 0;
        if (total > 0) {
            for (int bin = 15; bin >= 0; --bin) {
                int c = g_hist1[b][tid][bin];
                if (cum + c >= k) { j1 = bin; break; }
                cum += c;
            }
        }
        sT[tid] = (j1 >= 0) ? min((j1 + 1) << 12, 65535) : 65535;
        sL[tid] = (j1 >= 0) ? (j1 << 12) : 65535;
    }
    __syncthreads();

    const unsigned TT01 = (unsigned)sT[0] | ((unsigned)sT[1] << 16);
    const unsigned LL01 = (unsigned)sL[0] | ((unsigned)sL[1] << 16);
    const unsigned TT23 = (unsigned)sT[2] | ((unsigned)sT[3] << 16);
    const unsigned LL23 = (unsigned)sL[2] | ((unsigned)sL[3] << 16);
    const unsigned TT44 = (unsigned)sT[4] | ((unsigned)sT[4] << 16);
    const unsigned LL44 = (unsigned)sL[4] | ((unsigned)sL[4] << 16);
    const int L0 = sL[0], L1 = sL[1], L2 = sL[2], L3 = sL[3], L4 = sL[4];

    const uint4* PA = g_packA + (size_t)b * (NPIX / 4);
    const uint4* PB = g_packB + (size_t)b * (NPIX / 4);
    const uint2* PC = g_packC + (size_t)b * (NPIX / 4);
    int* H0 = g_hist2[b][0]; int* H1 = g_hist2[b][1]; int* H2 = g_hist2[b][2];
    int* H3 = g_hist2[b][3]; int* H4 = g_hist2[b][4];

    unsigned s0 = 0, s1 = 0, s2 = 0, s3 = 0, s4 = 0;
    unsigned c01 = 0, c23 = 0, c44 = 0;
    const int fbase = chunk * PXB + tid;

#define PROCW(W, TT, LL, SLO, SHI, CACC, HLO, HHI, LLO, LHI) { \
    unsigned m_ = __vcmpgtu2((W), (TT)); \
    unsigned sel_ = (W) & m_; \
    SLO += sel_ & 0xFFFFu; SHI += sel_ >> 16; \
    CACC += m_ & 0x00010001u; \
    unsigned im_ = __vcmpgtu2((W), (LL)) ^ m_; \
    if (im_ & 0xFFFFu)      atomicAdd((HLO) + (int)(((W) & 0xFFFFu) - 1u) - (LLO), 1); \
    if (im_ & 0xFFFF0000u)  atomicAdd((HHI) + (int)((W) >> 16) - 1 - (LHI), 1); }

#pragma unroll 2
    for (int it = 0; it < PXB / TPB; ++it) {
        const int fi = fbase + it * 256;
        uint4 A = PA[fi], B = PB[fi];
        uint2 C = PC[fi];
        PROCW(A.x, TT01, LL01, s0, s1, c01, H0, H1, L0, L1)
        PROCW(A.y, TT01, LL01, s0, s1, c01, H0, H1, L0, L1)
        PROCW(A.z, TT01, LL01, s0, s1, c01, H0, H1, L0, L1)
        PROCW(A.w, TT01, LL01, s0, s1, c01, H0, H1, L0, L1)
        PROCW(B.x, TT23, LL23, s2, s3, c23, H2, H3, L2, L3)
        PROCW(B.y, TT23, LL23, s2, s3, c23, H2, H3, L2, L3)
        PROCW(B.z, TT23, LL23, s2, s3, c23, H2, H3, L2, L3)
        PROCW(B.w, TT23, LL23, s2, s3, c23, H2, H3, L2, L3)
        PROCW(C.x, TT44, LL44, s4, s4, c44, H4, H4, L4, L4)
        PROCW(C.y, TT44, LL44, s4, s4, c44, H4, H4, L4, L4)
    }
#undef PROCW

    int sAt[5];
    sAt[0] = (int)(s0 - (c01 & 0xFFFFu));
    sAt[1] = (int)(s1 - (c01 >> 16));
    sAt[2] = (int)(s2 - (c23 & 0xFFFFu));
    sAt[3] = (int)(s3 - (c23 >> 16));
    sAt[4] = (int)(s4 - ((c44 & 0xFFFFu) + (c44 >> 16)));

#pragma unroll
    for (int ch = 0; ch < 5; ++ch) {
        int v = sAt[ch];
        for (int o = 16; o; o >>= 1) v += __shfl_down_sync(FULLMASK, v, o);
        if (lane == 0) red[ch * 8 + warp] = v;
    }
    __syncthreads();
    if (tid < 5) {
        int v = 0;
        for (int w2 = 0; w2 < 8; ++w2) v += red[tid * 8 + w2];
        atomicAdd(&g_sumA[b][tid], (float)v);
    }
}

// ---------------- kernel DE: topk scan + (last block per batch) stats/MLP ---
// 80 blocks (one per (b,ch)). D-scan register-resident + self-cleaning; the
// LAST finisher per batch continues into the E body (stats/LN/MLP/outputs).
__global__ void __launch_bounds__(256, 1)
kernelDE(const float* __restrict__ ln_w, const float* __restrict__ ln_b,
         const float* __restrict__ w1,   const float* __restrict__ b1,
         const float* __restrict__ w2,   const float* __restrict__ b2,
         float* __restrict__ out) {
    __shared__ int wtot[8];
    __shared__ float scontrib[8];
    __shared__ int sInfo[2];   // r, j1
    __shared__ int sLast;
    const int bc = blockIdx.x, b = bc / 5, ch = bc % 5;
    const int tid = threadIdx.x, warp = tid >> 5, lane = tid & 31;
    int* __restrict__ H = g_hist2[b][ch];

    if (tid == 0) {
        int total = g_cnt[b];
        int k = max(1, (int)rintf((float)total * 0.1f));
        int j1 = -1, cum = 0;
        if (total > 0) {
            for (int bin = 15; bin >= 0; --bin) {
                int c = g_hist1[b][ch][bin];
                if (cum + c >= k) { j1 = bin; break; }
                cum += c;
            }
        }
        sInfo[0] = k - cum;   // r
        sInfo[1] = j1;
    }

    // load 16 bins into registers; local count + weighted sum; zero behind us
    const int lo = 4080 - 16 * tid;
    int v[16];
    int cnt = 0; float wsum = 0.f;
    int4* H4 = (int4*)(H + lo);
    const int4 zero4 = make_int4(0, 0, 0, 0);
#pragma unroll
    for (int i = 0; i < 4; ++i) {
        int4 t = H4[i];
        v[4 * i] = t.x; v[4 * i + 1] = t.y; v[4 * i + 2] = t.z; v[4 * i + 3] = t.w;
        int code = lo + 4 * i;
        cnt += t.x + t.y + t.z + t.w;
        wsum += (float)t.x * (float)code + (float)t.y * (float)(code + 1)
              + (float)t.z * (float)(code + 2) + (float)t.w * (float)(code + 3);
        H4[i] = zero4;   // self-clean (thread-exclusive bins)
    }

    // inclusive prefix over 256 threads (warp shfl scan + warp-total offsets)
    int incl = cnt;
#pragma unroll
    for (int o = 1; o < 32; o <<= 1) {
        int t = __shfl_up_sync(FULLMASK, incl, o);
        if (lane >= o) incl += t;
    }
    if (lane == 31) wtot[warp] = incl;
    __syncthreads();
    // hist1[b][ch] fully consumed by tid 0 before the barrier -> zero it now
    if (tid >= 32 && tid < 48) g_hist1[b][ch][tid - 32] = 0;
    int woff = 0;
#pragma unroll
    for (int w = 0; w < 8; ++w) woff += (w < warp) ? wtot[w] : 0;
    incl += woff;
    const int excl = incl - cnt;

    const int r = sInfo[0], j1 = sInfo[1];
    float contrib = 0.f;
    if (j1 >= 0) {
        if (incl <= r) {
            contrib = wsum;
        } else if (excl < r) {
            int need = r - excl;
#pragma unroll
            for (int i = 15; i >= 0; --i) {
                int take = max(0, min(v[i], need));
                contrib += (float)take * (float)(lo + i);
                need -= take;
            }
        }
    }
    // block reduce contributions
    for (int o = 16; o; o >>= 1) contrib += __shfl_down_sync(FULLMASK, contrib, o);
    if (lane == 0) scontrib[warp] = contrib;
    __syncthreads();
    if (tid == 0) {
        float sA = g_sumA[b][ch];
        g_sumA[b][ch] = 0.f;          // same-thread same-address: safe
        float tk = 0.f;
        if (j1 >= 0) {
            float rs = 0.f;
#pragma unroll
            for (int w = 0; w < 8; ++w) rs += scontrib[w];
            int total = g_cnt[b];
            int k = max(1, (int)rintf((float)total * 0.1f));
            float full = rs + (float)r * (float)(j1 << 12);
            tk = (sA + full) * INV65534 / (float)k;
        }
        g_topk[b][ch] = tk;
        __threadfence();              // publish topk before counter bump
        int old = atomicAdd(&g_done[b], 1);
        sLast = (old == 4) ? 1 : 0;
    }
    __syncthreads();
    if (!sLast) return;

    // ================= E body: this block is the last finisher for batch b ==
    __shared__ float stats[18], normed[18], h1s[256];
    __shared__ float4 sred[256];

    if (tid < 32) {
        __threadfence();              // acquire: make peers' g_topk visible
        // ---- PHASE 1: ALL reads into registers (no stores yet) ----
        const int total = g_cnt[b];
        const float st = fmaxf((float)total, 1.f);
        float val = 0.f;
        if (tid < 4)        val = g_clsSum[b][tid] / st;
        else if (tid < 8)   val = __int_as_float(g_clsMax[b][tid - 4]);
        else if (tid < 12)  val = g_topk[b][tid - 8];
        else if (tid == 12) val = g_sevSum[b] / st;
        else if (tid == 13) val = __int_as_float(g_sevMax[b]);
        else if (tid == 14) val = g_topk[b][4];
        else if (tid == 15) val = g_dmg[b] / st;
        else if (tid == 16) val = g_high[b] / st;
        else if (tid == 17) val = (float)total / (float)NPIX;

        __syncwarp();                 // reads complete before self-clean stores

        // ---- PHASE 2: self-clean stores ----
        if (tid < 4)        g_clsSum[b][tid] = 0.f;
        else if (tid < 8)   g_clsMax[b][tid - 4] = 0;
        else if (tid == 12) g_sevSum[b] = 0.f;
        else if (tid == 13) g_sevMax[b] = 0;
        else if (tid == 15) g_dmg[b] = 0.f;
        else if (tid == 16) g_high[b] = 0.f;
        else if (tid == 17) g_cnt[b] = 0;
        else if (tid == 18) g_done[b] = 0;

        if (tid < 18) stats[tid] = val;

        // LN via warp reductions (lanes >=18 contribute 0)
        float x = (tid < 18) ? val : 0.f;
        float s = x;
#pragma unroll
        for (int o = 16; o; o >>= 1) s += __shfl_xor_sync(FULLMASK, s, o);
        float mu = s * (1.0f / 18.0f);
        float d = (tid < 18) ? (x - mu) : 0.f;
        float vsum = d * d;
#pragma unroll
        for (int o = 16; o; o >>= 1) vsum += __shfl_xor_sync(FULLMASK, vsum, o);
        float rstd = rsqrtf(vsum * (1.0f / 18.0f) + 1e-5f);
        if (tid < 18) normed[tid] = (x - mu) * rstd * ln_w[tid] + ln_b[tid];
    }
    __syncthreads();

    // layer 1: 18 -> 256, exact gelu
    {
        float a0 = b1[tid], a1 = 0.f;
#pragma unroll
        for (int i = 0; i < 18; i += 2) {
            a0 = fmaf(normed[i],     w1[i * 256 + tid],       a0);
            a1 = fmaf(normed[i + 1], w1[(i + 1) * 256 + tid], a1);
        }
        float acc = a0 + a1;
        h1s[tid] = 0.5f * acc * (1.0f + erff(acc * 0.70710678118654752f));
    }
    __syncthreads();

    // layer 2: 256 -> 256. Double-buffered float4 loads of w2.
    {
        const int g = tid >> 6, j = tid & 63;
        const float4* __restrict__ W2 =
            (const float4*)w2 + (size_t)(g * 64) * 64 + j;   // step 64 per k
        float4 cur[4], nxt[4];
#pragma unroll
        for (int q = 0; q < 4; ++q) cur[q] = W2[q * 64];
        float4 c0 = make_float4(0.f, 0.f, 0.f, 0.f);
        float4 c1 = make_float4(0.f, 0.f, 0.f, 0.f);
#pragma unroll
        for (int base = 0; base < 64; base += 4) {
            if (base + 4 < 64) {
#pragma unroll
                for (int q = 0; q < 4; ++q) nxt[q] = W2[(base + 4 + q) * 64];
            }
#pragma unroll
            for (int q = 0; q < 4; ++q) {
                const float h = h1s[g * 64 + base + q];
                float4 w = cur[q];
                if (q & 1) {
                    c1.x = fmaf(h, w.x, c1.x); c1.y = fmaf(h, w.y, c1.y);
                    c1.z = fmaf(h, w.z, c1.z); c1.w = fmaf(h, w.w, c1.w);
                } else {
                    c0.x = fmaf(h, w.x, c0.x); c0.y = fmaf(h, w.y, c0.y);
                    c0.z = fmaf(h, w.z, c0.z); c0.w = fmaf(h, w.w, c0.w);
                }
            }
#pragma unroll
            for (int q = 0; q < 4; ++q) cur[q] = nxt[q];
        }
        sred[tid] = make_float4(c0.x + c1.x, c0.y + c1.y, c0.z + c1.z, c0.w + c1.w);
    }
    __syncthreads();
    if (tid < 64) {
        const int j = tid;
        float4 c0 = sred[j], c1 = sred[64 + j], c2 = sred[128 + j], c3 = sred[192 + j];
        float4 bb = ((const float4*)b2)[j];
        float4 r4;
        r4.x = bb.x + ((c0.x + c1.x) + (c2.x + c3.x));
        r4.y = bb.y + ((c0.y + c1.y) + (c2.y + c3.y));
        r4.z = bb.z + ((c0.z + c1.z) + (c2.z + c3.z));
        r4.w = bb.w + ((c0.w + c1.w) + (c2.w + c3.w));
        ((float4*)(out + BATCH * 18 + b * 256))[j] = r4;
    }
    if (tid < 18) out[b * 18 + tid] = stats[tid];
    if (tid == 0) {
        const int base = BATCH * 18 + BATCH * 256;
        out[base + b]             = stats[15];
        out[base + BATCH + b]     = stats[16];
        out[base + 2 * BATCH + b] = stats[17];
    }
}

// ---------------- launch ----------------------------------------------------
extern "C" void kernel_launch(void* const* d_in, const int* in_sizes, int n_in,
                              void* d_out, int out_size) {
    const float* logits = (const float*)d_in[0];
    const float* sevm   = (const float*)d_in[1];
    const float* maskm  = (const float*)d_in[2];
    const float* ln_w   = (const float*)d_in[3];
    const float* ln_b   = (const float*)d_in[4];
    const float* w1     = (const float*)d_in[5];
    const float* b1     = (const float*)d_in[6];
    const float* w2     = (const float*)d_in[7];
    const float* b2     = (const float*)d_in[8];
    float* out = (float*)d_out;

    dim3 g(CHUNKS, BATCH);
    passA<<<g, TPB>>>(logits, sevm, maskm);
    passC<<<g, TPB>>>();
    kernelDE<<<80, 256>>>(ln_w, ln_b, w1, b1, w2, b2, out);
}